// round 3
// baseline (speedup 1.0000x reference)
#include <cuda_runtime.h>

// SuperpixelPooling: out[b,l,c] = mean over pixels p with label[b,p]==l of x[b,c,p]
// x: [B, C, H, W] float32, labels: [B, 1, H, W] int64 (or int32 if jax x64 off)
// out: [B, L, C] float32

#define BB 4
#define CC 128
#define HW (512 * 512)
#define LL 512

__device__ int g_cnt[BB * LL];   // per (b, label) pixel counts
__device__ int g_is64;           // 1 if labels are int64, 0 if int32

// ---------------------------------------------------------------------------
// Detect label dtype: for int64 labels in [0,512), every odd 32-bit word is 0.
// For int32 labels, odd words are random labels (all-zero prob ~ (1/512)^4096).
// ---------------------------------------------------------------------------
__global__ void detect_kernel(const unsigned* __restrict__ lab32) {
    __shared__ int any;
    if (threadIdx.x == 0) any = 0;
    __syncthreads();
    int found = 0;
    for (int i = threadIdx.x; i < 4096; i += blockDim.x) {
        if (lab32[2 * i + 1] != 0u) found = 1;
    }
    if (found) atomicOr(&any, 1);
    __syncthreads();
    if (threadIdx.x == 0) g_is64 = any ? 0 : 1;
}

__device__ __forceinline__ int get_label(const unsigned* __restrict__ lab32,
                                         long p, int is64) {
    return is64 ? (int)lab32[2 * p] : (int)lab32[p];
}

// ---------------------------------------------------------------------------
// Zero the output accumulator and the counts.
// ---------------------------------------------------------------------------
__global__ void zero_kernel(float* __restrict__ out) {
    int i = blockIdx.x * blockDim.x + threadIdx.x;
    if (i < BB * LL * CC) out[i] = 0.0f;
    if (i < BB * LL) g_cnt[i] = 0;
}

// ---------------------------------------------------------------------------
// Per-(b,label) counts via per-CTA shared histogram.
// Grid: (HW / (256*8), BB), block 256; each thread handles 8 pixels.
// ---------------------------------------------------------------------------
__global__ void __launch_bounds__(256) count_kernel(const unsigned* __restrict__ lab32) {
    __shared__ int h[LL];
    int tid = threadIdx.x;
    for (int i = tid; i < LL; i += blockDim.x) h[i] = 0;
    __syncthreads();

    int b = blockIdx.y;
    int is64 = g_is64;
    long base = (long)b * HW + (long)blockIdx.x * (blockDim.x * 8);
    #pragma unroll
    for (int j = 0; j < 8; j++) {
        long p = base + (long)j * blockDim.x + tid;
        int l = get_label(lab32, p, is64);
        atomicAdd(&h[l & (LL - 1)], 1);
    }
    __syncthreads();
    for (int i = tid; i < LL; i += blockDim.x)
        if (h[i]) atomicAdd(&g_cnt[b * LL + i], h[i]);
}

// ---------------------------------------------------------------------------
// 128-bit vector global reduction (sm_90+): 4 channel partial sums per op.
// ---------------------------------------------------------------------------
__device__ __forceinline__ void red4(float* a, float v0, float v1, float v2, float v3) {
    asm volatile("red.global.add.v4.f32 [%0], {%1, %2, %3, %4};"
                 :: "l"(a), "f"(v0), "f"(v1), "f"(v2), "f"(v3)
                 : "memory");
}

// ---------------------------------------------------------------------------
// Sums: one thread per pixel, loops over all 128 channels in groups of 4.
// x loads are coalesced (4 contiguous 128B segments per warp per group).
// Grid: (HW/256, BB), block 256.
// ---------------------------------------------------------------------------
__global__ void __launch_bounds__(256) sums_kernel(const float* __restrict__ x,
                                                   const unsigned* __restrict__ lab32,
                                                   float* __restrict__ out) {
    int p = blockIdx.x * blockDim.x + threadIdx.x;   // pixel within batch
    int b = blockIdx.y;
    int is64 = g_is64;

    int l = get_label(lab32, (long)b * HW + p, is64) & (LL - 1);
    const float* xb = x + (long)b * CC * HW + p;
    float* o = out + ((long)b * LL + l) * CC;

    #pragma unroll 4
    for (int c = 0; c < CC; c += 4) {
        float v0 = xb[(long)(c + 0) * HW];
        float v1 = xb[(long)(c + 1) * HW];
        float v2 = xb[(long)(c + 2) * HW];
        float v3 = xb[(long)(c + 3) * HW];
        red4(o + c, v0, v1, v2, v3);
    }
}

// ---------------------------------------------------------------------------
// Normalize in place: out[b,l,c] /= max(count[b,l], 1)
// ---------------------------------------------------------------------------
__global__ void norm_kernel(float* __restrict__ out) {
    int i = blockIdx.x * blockDim.x + threadIdx.x;
    if (i < BB * LL * CC) {
        int bl = i / CC;
        float cnt = (float)g_cnt[bl];
        out[i] = out[i] / fmaxf(cnt, 1.0f);
    }
}

extern "C" void kernel_launch(void* const* d_in, const int* in_sizes, int n_in,
                              void* d_out, int out_size) {
    const float* x = (const float*)d_in[0];
    const unsigned* lab32 = (const unsigned*)d_in[1];
    float* out = (float*)d_out;

    detect_kernel<<<1, 256>>>(lab32);

    int nz = BB * LL * CC;  // 262144
    zero_kernel<<<(nz + 255) / 256, 256>>>(out);

    dim3 cgrid(HW / (256 * 8), BB);
    count_kernel<<<cgrid, 256>>>(lab32);

    dim3 sgrid(HW / 256, BB);
    sums_kernel<<<sgrid, 256>>>(x, lab32, out);

    norm_kernel<<<(nz + 255) / 256, 256>>>(out);
}

// round 5
// speedup vs baseline: 1.4204x; 1.4204x over previous
#include <cuda_runtime.h>

// SuperpixelPooling: out[b,l,c] = mean over pixels p with label[b,p]==l of x[b,c,p]
// x: [B, C, H, W] float32, labels: [B, 1, H, W] int64 (or int32), out: [B, L, C] f32
//
// Strategy: per-CTA counting sort of a 4096-pixel tile by label, then per
// 4-channel group stage values in smem (SoA) and emit ONE red.global.add.v4
// per label-run instead of one per pixel (~5.5x fewer L2 atomics).

#define BB 4
#define CC 128
#define HWP (512 * 512)
#define LL 512
#define TPX 4096                 // pixels per CTA tile
#define NT 256                   // threads per CTA
#define RWIN (TPX / NT)          // 16 sorted positions per thread

__device__ int g_cnt[BB * LL];   // per (b, label) pixel counts
__device__ int g_is64;           // 1 if labels are int64, 0 if int32

// ---------------------------------------------------------------------------
// Detect label dtype: int64 labels < 512 have all odd 32-bit words == 0.
// ---------------------------------------------------------------------------
__global__ void detect_kernel(const unsigned* __restrict__ lab32) {
    __shared__ int any;
    if (threadIdx.x == 0) any = 0;
    __syncthreads();
    int found = 0;
    for (int i = threadIdx.x; i < 4096; i += blockDim.x)
        if (lab32[2 * i + 1] != 0u) found = 1;
    if (found) atomicOr(&any, 1);
    __syncthreads();
    if (threadIdx.x == 0) g_is64 = any ? 0 : 1;
}

__device__ __forceinline__ int get_label(const unsigned* __restrict__ lab32,
                                         long p, int is64) {
    return (is64 ? (int)lab32[2 * p] : (int)lab32[p]) & (LL - 1);
}

__global__ void zero_kernel(float* __restrict__ out) {
    int i = blockIdx.x * blockDim.x + threadIdx.x;
    if (i < BB * LL * CC) out[i] = 0.0f;
    if (i < BB * LL) g_cnt[i] = 0;
}

__device__ __forceinline__ void red4(float* a, float v0, float v1, float v2, float v3) {
    asm volatile("red.global.add.v4.f32 [%0], {%1, %2, %3, %4};"
                 :: "l"(a), "f"(v0), "f"(v1), "f"(v2), "f"(v3)
                 : "memory");
}

// ---------------------------------------------------------------------------
// Main pooling kernel. Grid: (HWP/TPX = 64, BB), block NT=256.
// Dynamic smem layout:
//   stage : 4 * TPX floats (SoA per channel of group)       65536 B
//   spix  : TPX u32, sorted (label<<16)|local_px            16384 B
//   lab16 : TPX u16, raw labels of tile                      8192 B
//   hist  : LL int                                           2048 B
//   ofs   : LL int (scan result, consumed by scatter)        2048 B
//   scan  : NT int                                           1024 B
// ---------------------------------------------------------------------------
extern __shared__ char smem_raw[];

__global__ void __launch_bounds__(NT)
pool_kernel(const float* __restrict__ x, const unsigned* __restrict__ lab32,
            float* __restrict__ out) {
    float*          stage = (float*)smem_raw;
    unsigned*       spix  = (unsigned*)(smem_raw + 4 * TPX * 4);
    unsigned short* lab16 = (unsigned short*)((char*)spix + TPX * 4);
    int*            hist  = (int*)((char*)lab16 + TPX * 2);
    int*            ofs   = hist + LL;
    int*            scan  = ofs + LL;

    const int t = threadIdx.x;
    const int b = blockIdx.y;
    const long tile_base = (long)blockIdx.x * TPX;
    const int is64 = g_is64;

    // ---- 1. labels + histogram ----
    for (int i = t; i < LL; i += NT) hist[i] = 0;
    __syncthreads();
    #pragma unroll
    for (int j = 0; j < RWIN; j++) {
        int i = t + j * NT;
        int l = get_label(lab32, (long)b * HWP + tile_base + i, is64);
        lab16[i] = (unsigned short)l;
        atomicAdd(&hist[l], 1);
    }
    __syncthreads();

    // counts -> global (tile partial)
    for (int i = t; i < LL; i += NT) {
        int h = hist[i];
        if (h) atomicAdd(&g_cnt[b * LL + i], h);
    }

    // ---- 2. exclusive scan of hist into ofs (pair per thread) ----
    int h0 = hist[2 * t], h1 = hist[2 * t + 1];
    int ps = h0 + h1;
    scan[t] = ps;
    __syncthreads();
    for (int d = 1; d < NT; d <<= 1) {
        int v = (t >= d) ? scan[t - d] : 0;
        __syncthreads();
        scan[t] += v;
        __syncthreads();
    }
    int excl = scan[t] - ps;
    ofs[2 * t] = excl;
    ofs[2 * t + 1] = excl + h0;
    __syncthreads();

    // ---- 3. scatter sorted (label, px) pairs ----
    #pragma unroll
    for (int j = 0; j < RWIN; j++) {
        int i = t + j * NT;
        int l = lab16[i];
        int pos = atomicAdd(&ofs[l], 1);
        spix[pos] = ((unsigned)l << 16) | (unsigned)i;
    }
    __syncthreads();

    // ---- 4. per channel-group: stage values, run-merge, emit red4 ----
    const float* xb = x + (long)b * CC * HWP + tile_base;
    float* ob = out + (long)b * LL * CC;

    for (int cg = 0; cg < CC / 4; cg++) {
        // stage 4 channel planes (SoA), coalesced 128-bit copies
        #pragma unroll
        for (int c = 0; c < 4; c++) {
            const float4* src = (const float4*)(xb + (long)(cg * 4 + c) * HWP);
            float4* dst = (float4*)(stage + c * TPX);
            #pragma unroll
            for (int j = 0; j < TPX / 4 / NT; j++) {   // 4 iters
                int f = t + j * NT;
                dst[f] = src[f];
            }
        }
        __syncthreads();

        // walk sorted window, accumulate runs of equal label
        int pos0 = t * RWIN;
        float a0 = 0.f, a1 = 0.f, a2 = 0.f, a3 = 0.f;
        int cur = -1;
        #pragma unroll
        for (int j = 0; j < RWIN; j++) {
            unsigned sp = spix[pos0 + j];
            int l  = (int)(sp >> 16);
            int px = (int)(sp & 0xFFFFu);
            float v0 = stage[0 * TPX + px];
            float v1 = stage[1 * TPX + px];
            float v2 = stage[2 * TPX + px];
            float v3 = stage[3 * TPX + px];
            if (l != cur) {
                if (cur >= 0) red4(ob + (long)cur * CC + cg * 4, a0, a1, a2, a3);
                cur = l; a0 = v0; a1 = v1; a2 = v2; a3 = v3;
            } else {
                a0 += v0; a1 += v1; a2 += v2; a3 += v3;
            }
        }
        red4(ob + (long)cur * CC + cg * 4, a0, a1, a2, a3);
        __syncthreads();   // stage reused next cg
    }
}

// ---------------------------------------------------------------------------
// Normalize in place: out[b,l,c] /= max(count[b,l], 1)
// ---------------------------------------------------------------------------
__global__ void norm_kernel(float* __restrict__ out) {
    int i = blockIdx.x * blockDim.x + threadIdx.x;
    if (i < BB * LL * CC) {
        float cnt = (float)g_cnt[i / CC];
        out[i] = out[i] / fmaxf(cnt, 1.0f);
    }
}

extern "C" void kernel_launch(void* const* d_in, const int* in_sizes, int n_in,
                              void* d_out, int out_size) {
    const float* x = (const float*)d_in[0];
    const unsigned* lab32 = (const unsigned*)d_in[1];
    float* out = (float*)d_out;

    static const int SMEM_BYTES =
        4 * TPX * 4 + TPX * 4 + TPX * 2 + LL * 4 + LL * 4 + NT * 4;  // 95232

    cudaFuncSetAttribute(pool_kernel,
                         cudaFuncAttributeMaxDynamicSharedMemorySize, SMEM_BYTES);

    detect_kernel<<<1, 256>>>(lab32);

    int nz = BB * LL * CC;
    zero_kernel<<<(nz + 255) / 256, 256>>>(out);

    dim3 grid(HWP / TPX, BB);
    pool_kernel<<<grid, NT, SMEM_BYTES>>>(x, lab32, out);

    norm_kernel<<<(nz + 255) / 256, 256>>>(out);
}

// round 7
// speedup vs baseline: 1.4731x; 1.0371x over previous
#include <cuda_runtime.h>

// SuperpixelPooling: out[b,l,c] = mean over pixels p with label[b,p]==l of x[b,c,p]
// x: [B, C, H, W] float32, labels: [B, 1, H, W] int64 (or int32), out: [B, L, C] f32
//
// Per-CTA counting sort of a 4096-pixel tile by label; per 4-channel group,
// stage values in smem as AoS float4 (XOR-swizzled) and emit ONE
// red.global.add.v4 per label-run (~5.5x fewer L2 atomics than per-pixel).
// R7: conflict-free spix layout (transposed) + single LDS.128 gather +
// phase-conflict-free STS swizzle (px ^ ((px>>3)&7)).

#define BB 4
#define CC 128
#define HWP (512 * 512)
#define LL 512
#define TPX 4096                 // pixels per CTA tile
#define NT 256                   // threads per CTA
#define RWIN (TPX / NT)          // 16 sorted positions per thread

__device__ int g_cnt[BB * LL];   // per (b, label) pixel counts
__device__ int g_is64;           // 1 if labels are int64, 0 if int32

// swizzle for AoS float4 stage: e&7 permutes within each 8-lane STS.128 phase
__device__ __forceinline__ int swz(int px) { return px ^ ((px >> 3) & 7); }

// ---------------------------------------------------------------------------
// Detect label dtype: int64 labels < 512 have all odd 32-bit words == 0.
// ---------------------------------------------------------------------------
__global__ void detect_kernel(const unsigned* __restrict__ lab32) {
    __shared__ int any;
    if (threadIdx.x == 0) any = 0;
    __syncthreads();
    int found = 0;
    for (int i = threadIdx.x; i < 4096; i += blockDim.x)
        if (lab32[2 * i + 1] != 0u) found = 1;
    if (found) atomicOr(&any, 1);
    __syncthreads();
    if (threadIdx.x == 0) g_is64 = any ? 0 : 1;
}

__device__ __forceinline__ int get_label(const unsigned* __restrict__ lab32,
                                         long p, int is64) {
    return (is64 ? (int)lab32[2 * p] : (int)lab32[p]) & (LL - 1);
}

__global__ void zero_kernel(float4* __restrict__ out) {
    int i = blockIdx.x * blockDim.x + threadIdx.x;   // 65536 float4
    out[i] = make_float4(0.f, 0.f, 0.f, 0.f);
    if (i < BB * LL) g_cnt[i] = 0;
}

__device__ __forceinline__ void red4(float* a, float v0, float v1, float v2, float v3) {
    asm volatile("red.global.add.v4.f32 [%0], {%1, %2, %3, %4};"
                 :: "l"(a), "f"(v0), "f"(v1), "f"(v2), "f"(v3)
                 : "memory");
}

// ---------------------------------------------------------------------------
// Main pooling kernel. Grid: (HWP/TPX = 64, BB), block NT=256.
// Dynamic smem:
//   stage : TPX float4 AoS (4 channels), swizzled              65536 B
//   spixT : TPX u32, sorted (label<<16)|px, TRANSPOSED layout  16384 B
//   lab16 : TPX u16                                             8192 B
//   hist/ofs/scan                                               5120 B
// Total 95232 B -> occupancy 2 CTA/SM.
// ---------------------------------------------------------------------------
extern __shared__ char smem_raw[];

__global__ void __launch_bounds__(NT)
pool_kernel(const float* __restrict__ x, const unsigned* __restrict__ lab32,
            float* __restrict__ out) {
    float4*         stage = (float4*)smem_raw;
    unsigned*       spixT = (unsigned*)(smem_raw + TPX * 16);
    unsigned short* lab16 = (unsigned short*)((char*)spixT + TPX * 4);
    int*            hist  = (int*)((char*)lab16 + TPX * 2);
    int*            ofs   = hist + LL;
    int*            scan  = ofs + LL;

    const int t = threadIdx.x;
    const int b = blockIdx.y;
    const long tile_base = (long)blockIdx.x * TPX;
    const int is64 = g_is64;

    // ---- 1. labels + histogram ----
    for (int i = t; i < LL; i += NT) hist[i] = 0;
    __syncthreads();
    #pragma unroll
    for (int j = 0; j < RWIN; j++) {
        int i = t + j * NT;
        int l = get_label(lab32, (long)b * HWP + tile_base + i, is64);
        lab16[i] = (unsigned short)l;
        atomicAdd(&hist[l], 1);
    }
    __syncthreads();

    // counts -> global (tile partial)
    for (int i = t; i < LL; i += NT) {
        int h = hist[i];
        if (h) atomicAdd(&g_cnt[b * LL + i], h);
    }

    // ---- 2. exclusive scan of hist into ofs (pair per thread) ----
    int h0 = hist[2 * t], h1 = hist[2 * t + 1];
    int ps = h0 + h1;
    scan[t] = ps;
    __syncthreads();
    for (int d = 1; d < NT; d <<= 1) {
        int v = (t >= d) ? scan[t - d] : 0;
        __syncthreads();
        scan[t] += v;
        __syncthreads();
    }
    int excl = scan[t] - ps;
    ofs[2 * t] = excl;
    ofs[2 * t + 1] = excl + h0;
    __syncthreads();

    // ---- 3. scatter sorted pairs into TRANSPOSED layout:
    //        sorted position p lives at spixT[(p%16)*256 + p/16]
    //        so the gather at step j reads spixT[j*256 + t] (lane-contiguous).
    #pragma unroll
    for (int j = 0; j < RWIN; j++) {
        int i = t + j * NT;
        int l = lab16[i];
        int pos = atomicAdd(&ofs[l], 1);
        spixT[((pos & (RWIN - 1)) << 8) | (pos >> 4)] =
            ((unsigned)l << 16) | (unsigned)i;
    }
    __syncthreads();

    // ---- 4. per 4-channel group: stage AoS float4 (swizzled), run-merge ----
    const float* xb = x + (long)b * CC * HWP + tile_base;
    float* ob = out + (long)b * LL * CC;

    for (int cg = 0; cg < CC / 4; cg++) {
        const float4* p0 = (const float4*)(xb + (long)(cg * 4 + 0) * HWP);
        const float4* p1 = (const float4*)(xb + (long)(cg * 4 + 1) * HWP);
        const float4* p2 = (const float4*)(xb + (long)(cg * 4 + 2) * HWP);
        const float4* p3 = (const float4*)(xb + (long)(cg * 4 + 3) * HWP);

        // stage: coalesced plane loads, register 4x4 transpose, swizzled STS.128
        #pragma unroll
        for (int k = 0; k < TPX / 4 / NT; k++) {       // 4 chunks
            int f = k * NT + t;                         // float4 index, lane-contig
            float4 a = p0[f], b4 = p1[f], c4 = p2[f], d4 = p3[f];
            int px = 4 * f;
            stage[swz(px + 0)] = make_float4(a.x, b4.x, c4.x, d4.x);
            stage[swz(px + 1)] = make_float4(a.y, b4.y, c4.y, d4.y);
            stage[swz(px + 2)] = make_float4(a.z, b4.z, c4.z, d4.z);
            stage[swz(px + 3)] = make_float4(a.w, b4.w, c4.w, d4.w);
        }
        __syncthreads();

        // walk this thread's contiguous sorted window [t*16, t*16+16)
        float a0 = 0.f, a1 = 0.f, a2 = 0.f, a3 = 0.f;
        int cur = -1;
        #pragma unroll
        for (int j = 0; j < RWIN; j++) {
            unsigned sp = spixT[j * NT + t];            // conflict-free
            int l  = (int)(sp >> 16);
            int px = (int)(sp & 0xFFFFu);
            float4 v = stage[swz(px)];                  // single LDS.128
            if (l != cur) {
                if (cur >= 0) red4(ob + (long)cur * CC + cg * 4, a0, a1, a2, a3);
                cur = l; a0 = v.x; a1 = v.y; a2 = v.z; a3 = v.w;
            } else {
                a0 += v.x; a1 += v.y; a2 += v.z; a3 += v.w;
            }
        }
        red4(ob + (long)cur * CC + cg * 4, a0, a1, a2, a3);
        __syncthreads();                                // stage reused next cg
    }
}

// ---------------------------------------------------------------------------
// Normalize in place (vectorized): out[b,l,c] /= max(count[b,l], 1)
// ---------------------------------------------------------------------------
__global__ void norm_kernel(float4* __restrict__ out) {
    int i = blockIdx.x * blockDim.x + threadIdx.x;   // 65536 float4
    float inv = 1.0f / fmaxf((float)g_cnt[i / (CC / 4)], 1.0f);
    float4 v = out[i];
    v.x *= inv; v.y *= inv; v.z *= inv; v.w *= inv;
    out[i] = v;
}

extern "C" void kernel_launch(void* const* d_in, const int* in_sizes, int n_in,
                              void* d_out, int out_size) {
    const float* x = (const float*)d_in[0];
    const unsigned* lab32 = (const unsigned*)d_in[1];
    float* out = (float*)d_out;

    static const int SMEM_BYTES =
        TPX * 16 + TPX * 4 + TPX * 2 + LL * 4 + LL * 4 + NT * 4;  // 95232

    cudaFuncSetAttribute(pool_kernel,
                         cudaFuncAttributeMaxDynamicSharedMemorySize, SMEM_BYTES);

    detect_kernel<<<1, 256>>>(lab32);

    int nv4 = BB * LL * CC / 4;   // 65536 float4
    zero_kernel<<<nv4 / 256, 256>>>((float4*)out);

    dim3 grid(HWP / TPX, BB);
    pool_kernel<<<grid, NT, SMEM_BYTES>>>(x, lab32, out);

    norm_kernel<<<nv4 / 256, 256>>>((float4*)out);
}

// round 11
// speedup vs baseline: 1.7005x; 1.1544x over previous
#include <cuda_runtime.h>

// SuperpixelPooling: out[b,l,c] = mean over pixels p with label[b,p]==l of x[b,c,p]
// x: [B, C, H, W] float32, labels: [B, 1, H, W] int64 (or int32), out: [B, L, C] f32
//
// Per-CTA counting sort of a 4096-pixel tile by label; per 4-channel group,
// stage values in smem as AoS float4 (XOR-swizzled) and emit ONE
// red.global.add.v4 per label-run (~5.5x fewer L2 atomics than per-pixel).
// R8/R11: register-prefetch software pipeline — next cg's LDGs issued before
// the gather phase so the DRAM stream overlaps the smem gather instead of
// alternating with it. Launch order puts pool_kernel at capture slot 4.

#define BB 4
#define CC 128
#define HWP (512 * 512)
#define LL 512
#define TPX 4096                 // pixels per CTA tile
#define NT 256                   // threads per CTA
#define RWIN (TPX / NT)          // 16 sorted positions per thread
#define NCHUNK (TPX / 4 / NT)    // 4 float4 chunks per thread per plane

__device__ int g_cnt[BB * LL];   // per (b, label) pixel counts
__device__ int g_is64;           // 1 if labels are int64, 0 if int32

// swizzle for AoS float4 stage: e&7 permutes within each 8-lane STS.128 phase
__device__ __forceinline__ int swz(int px) { return px ^ ((px >> 3) & 7); }

// ---------------------------------------------------------------------------
// Detect label dtype: int64 labels < 512 have all odd 32-bit words == 0.
// ---------------------------------------------------------------------------
__global__ void detect_kernel(const unsigned* __restrict__ lab32) {
    __shared__ int any;
    if (threadIdx.x == 0) any = 0;
    __syncthreads();
    int found = 0;
    for (int i = threadIdx.x; i < 4096; i += blockDim.x)
        if (lab32[2 * i + 1] != 0u) found = 1;
    if (found) atomicOr(&any, 1);
    __syncthreads();
    if (threadIdx.x == 0) g_is64 = any ? 0 : 1;
}

__device__ __forceinline__ int get_label(const unsigned* __restrict__ lab32,
                                         long p, int is64) {
    return (is64 ? (int)lab32[2 * p] : (int)lab32[p]) & (LL - 1);
}

__global__ void zero_out_kernel(float4* __restrict__ out) {
    int i = blockIdx.x * blockDim.x + threadIdx.x;   // 65536 float4
    out[i] = make_float4(0.f, 0.f, 0.f, 0.f);
}

__global__ void zero_cnt_kernel() {
    int i = blockIdx.x * blockDim.x + threadIdx.x;
    if (i < BB * LL) g_cnt[i] = 0;
}

__device__ __forceinline__ void red4(float* a, float v0, float v1, float v2, float v3) {
    asm volatile("red.global.add.v4.f32 [%0], {%1, %2, %3, %4};"
                 :: "l"(a), "f"(v0), "f"(v1), "f"(v2), "f"(v3)
                 : "memory");
}

// ---------------------------------------------------------------------------
// Main pooling kernel. Grid: (HWP/TPX = 64, BB), block NT=256, occ 2/SM.
// Dynamic smem:
//   stage : TPX float4 AoS (4 channels), swizzled              65536 B
//   spixT : TPX u32, sorted (label<<16)|px, TRANSPOSED layout  16384 B
//   lab16 : TPX u16                                             8192 B
//   hist/ofs/scan                                               5120 B
// ---------------------------------------------------------------------------
extern __shared__ char smem_raw[];

__global__ void __launch_bounds__(NT, 2)
pool_kernel(const float* __restrict__ x, const unsigned* __restrict__ lab32,
            float* __restrict__ out) {
    float4*         stage = (float4*)smem_raw;
    unsigned*       spixT = (unsigned*)(smem_raw + TPX * 16);
    unsigned short* lab16 = (unsigned short*)((char*)spixT + TPX * 4);
    int*            hist  = (int*)((char*)lab16 + TPX * 2);
    int*            ofs   = hist + LL;
    int*            scan  = ofs + LL;

    const int t = threadIdx.x;
    const int b = blockIdx.y;
    const long tile_base = (long)blockIdx.x * TPX;
    const int is64 = g_is64;

    // ---- 1. labels + histogram ----
    for (int i = t; i < LL; i += NT) hist[i] = 0;
    __syncthreads();
    #pragma unroll
    for (int j = 0; j < RWIN; j++) {
        int i = t + j * NT;
        int l = get_label(lab32, (long)b * HWP + tile_base + i, is64);
        lab16[i] = (unsigned short)l;
        atomicAdd(&hist[l], 1);
    }
    __syncthreads();

    // counts -> global (tile partial)
    for (int i = t; i < LL; i += NT) {
        int h = hist[i];
        if (h) atomicAdd(&g_cnt[b * LL + i], h);
    }

    // ---- 2. exclusive scan of hist into ofs (pair per thread) ----
    int h0 = hist[2 * t], h1 = hist[2 * t + 1];
    int ps = h0 + h1;
    scan[t] = ps;
    __syncthreads();
    for (int d = 1; d < NT; d <<= 1) {
        int v = (t >= d) ? scan[t - d] : 0;
        __syncthreads();
        scan[t] += v;
        __syncthreads();
    }
    int excl = scan[t] - ps;
    ofs[2 * t] = excl;
    ofs[2 * t + 1] = excl + h0;
    __syncthreads();

    // ---- 3. scatter sorted pairs into TRANSPOSED layout:
    //        sorted position p lives at spixT[(p%16)*256 + p/16]
    //        so the gather at step j reads spixT[j*256 + t] (lane-contiguous).
    #pragma unroll
    for (int j = 0; j < RWIN; j++) {
        int i = t + j * NT;
        int l = lab16[i];
        int pos = atomicAdd(&ofs[l], 1);
        spixT[((pos & (RWIN - 1)) << 8) | (pos >> 4)] =
            ((unsigned)l << 16) | (unsigned)i;
    }

    // ---- 4. per 4-channel group: software-pipelined stage + run-merge ----
    const float4* xb4 = (const float4*)(x + (long)b * CC * HWP + tile_base);
    const long PLANE4 = HWP / 4;               // float4 per channel plane
    float* ob = out + (long)b * LL * CC;

    // prefetch registers for one full cg (4 planes x 4 chunks)
    float4 ra[NCHUNK], rb[NCHUNK], rc[NCHUNK], rd[NCHUNK];

    // prologue: load cg = 0
    {
        const float4* p0 = xb4;
        #pragma unroll
        for (int k = 0; k < NCHUNK; k++) {
            int f = k * NT + t;
            ra[k] = p0[f + 0 * PLANE4];
            rb[k] = p0[f + 1 * PLANE4];
            rc[k] = p0[f + 2 * PLANE4];
            rd[k] = p0[f + 3 * PLANE4];
        }
    }

    for (int cg = 0; cg < CC / 4; cg++) {
        __syncthreads();        // stage free (prev gather done); also covers sort
        // STS: register 4x4 transpose into swizzled AoS float4
        #pragma unroll
        for (int k = 0; k < NCHUNK; k++) {
            int px = 4 * (k * NT + t);
            stage[swz(px + 0)] = make_float4(ra[k].x, rb[k].x, rc[k].x, rd[k].x);
            stage[swz(px + 1)] = make_float4(ra[k].y, rb[k].y, rc[k].y, rd[k].y);
            stage[swz(px + 2)] = make_float4(ra[k].z, rb[k].z, rc[k].z, rd[k].z);
            stage[swz(px + 3)] = make_float4(ra[k].w, rb[k].w, rc[k].w, rd[k].w);
        }
        // prefetch next cg: LDGs in flight during the whole gather below
        if (cg + 1 < CC / 4) {
            const float4* p0 = xb4 + (long)(cg + 1) * 4 * PLANE4;
            #pragma unroll
            for (int k = 0; k < NCHUNK; k++) {
                int f = k * NT + t;
                ra[k] = p0[f + 0 * PLANE4];
                rb[k] = p0[f + 1 * PLANE4];
                rc[k] = p0[f + 2 * PLANE4];
                rd[k] = p0[f + 3 * PLANE4];
            }
        }
        __syncthreads();        // stage ready

        // walk this thread's contiguous sorted window [t*16, t*16+16)
        float a0 = 0.f, a1 = 0.f, a2 = 0.f, a3 = 0.f;
        int cur = -1;
        #pragma unroll
        for (int j = 0; j < RWIN; j++) {
            unsigned sp = spixT[j * NT + t];            // conflict-free
            int l  = (int)(sp >> 16);
            int px = (int)(sp & 0xFFFFu);
            float4 v = stage[swz(px)];                  // single LDS.128
            if (l != cur) {
                if (cur >= 0) red4(ob + (long)cur * CC + cg * 4, a0, a1, a2, a3);
                cur = l; a0 = v.x; a1 = v.y; a2 = v.z; a3 = v.w;
            } else {
                a0 += v.x; a1 += v.y; a2 += v.z; a3 += v.w;
            }
        }
        red4(ob + (long)cur * CC + cg * 4, a0, a1, a2, a3);
    }
}

// ---------------------------------------------------------------------------
// Normalize in place (vectorized): out[b,l,c] /= max(count[b,l], 1)
// ---------------------------------------------------------------------------
__global__ void norm_kernel(float4* __restrict__ out) {
    int i = blockIdx.x * blockDim.x + threadIdx.x;   // 65536 float4
    float inv = 1.0f / fmaxf((float)g_cnt[i / (CC / 4)], 1.0f);
    float4 v = out[i];
    v.x *= inv; v.y *= inv; v.z *= inv; v.w *= inv;
    out[i] = v;
}

extern "C" void kernel_launch(void* const* d_in, const int* in_sizes, int n_in,
                              void* d_out, int out_size) {
    const float* x = (const float*)d_in[0];
    const unsigned* lab32 = (const unsigned*)d_in[1];
    float* out = (float*)d_out;

    static const int SMEM_BYTES =
        TPX * 16 + TPX * 4 + TPX * 2 + LL * 4 + LL * 4 + NT * 4;  // 95232

    cudaFuncSetAttribute(pool_kernel,
                         cudaFuncAttributeMaxDynamicSharedMemorySize, SMEM_BYTES);

    int nv4 = BB * LL * CC / 4;   // 65536 float4

    // launch order chosen so pool_kernel is the 4th launch (ncu capture slot)
    detect_kernel<<<1, 256>>>(lab32);
    zero_out_kernel<<<nv4 / 256, 256>>>((float4*)out);
    zero_cnt_kernel<<<(BB * LL + 255) / 256, 256>>>();

    dim3 grid(HWP / TPX, BB);
    pool_kernel<<<grid, NT, SMEM_BYTES>>>(x, lab32, out);

    norm_kernel<<<nv4 / 256, 256>>>((float4*)out);
}